// round 3
// baseline (speedup 1.0000x reference)
#include <cuda_runtime.h>

#define BB 4
#define NCH 3
#define NCLS 20
#define HH 512
#define WW 512
#define MAXB 50
#define STRIPS 16
#define THREADS 256
#define NBLK (BB * MAXB * STRIPS)

__device__ float g_part[NBLK];
__device__ int g_count = 0;

__global__ void sel_fused_kernel(const float* __restrict__ y_fcn,
                                 const float* __restrict__ im_data,
                                 const int* __restrict__ gt_boxes,
                                 const int* __restrict__ num_boxes,
                                 float* __restrict__ out) {
    const int boxid = blockIdx.x;          // 0 .. B*MAXB-1
    const int strip = blockIdx.y;          // 0 .. STRIPS-1
    const int b = boxid / MAXB;
    const int j = boxid % MAXB;
    const int tid = threadIdx.x;
    const int lane = tid & 31;
    const int warp = tid >> 5;

    float acc = 0.0f;
    float denom = 1.0f;
    bool valid = (j < num_boxes[b]);

    int x1 = 0, r0 = 0, r1 = 0, wid = 0;
    const float* im0 = nullptr;
    const float* yf0 = nullptr;

    if (valid) {
        const int* g = gt_boxes + (size_t)boxid * 5;
        x1 = g[0];
        const int y1 = g[1], x2 = g[2], y2 = g[3], cls = g[4];
        const int hgt = y2 - y1;
        wid = x2 - x1;
        if (hgt > 0 && wid > 0) {
            const int rows_per = (hgt + STRIPS - 1) / STRIPS;
            r0 = y1 + strip * rows_per;
            r1 = min(r0 + rows_per, y2);
            denom = (float)(NCH * hgt * wid);
            const size_t plane = (size_t)HH * WW;
            im0 = im_data + (size_t)b * NCH * plane;
            yf0 = y_fcn + ((size_t)b * NCLS + cls) * NCH * plane;
        } else {
            valid = false;
        }
    }

    if (valid && r0 < r1) {
        const size_t plane = (size_t)HH * WW;
        const int total = (r1 - r0) * wid;
        for (int idx = tid; idx < total; idx += THREADS) {
            const int rr = idx / wid;
            const int cc = idx - rr * wid;
            const int off = (r0 + rr) * WW + x1 + cc;
#pragma unroll
            for (int n = 0; n < NCH; n++) {
                const float d = __ldg(im0 + (size_t)n * plane + off)
                              - __ldg(yf0 + (size_t)n * plane + off);
                acc += d * d;
            }
        }
    }

    // block reduction
    __shared__ float sm[THREADS / 32];
#pragma unroll
    for (int o = 16; o > 0; o >>= 1)
        acc += __shfl_down_sync(0xffffffffu, acc, o);
    if (lane == 0) sm[warp] = acc;
    __syncthreads();

    __shared__ bool is_last;
    if (tid == 0) {
        float s = 0.0f;
#pragma unroll
        for (int w = 0; w < THREADS / 32; w++) s += sm[w];
        // unconditional write: every slot refreshed every call
        g_part[boxid * STRIPS + strip] = s / denom;
        __threadfence();
        const int ticket = atomicAdd(&g_count, 1);
        is_last = (ticket == NBLK - 1);
    }
    __syncthreads();

    if (is_last) {
        __threadfence();  // make all g_part writes visible to whole block
        float s = 0.0f;
        for (int i = tid; i < NBLK; i += THREADS) s += g_part[i];
#pragma unroll
        for (int o = 16; o > 0; o >>= 1)
            s += __shfl_down_sync(0xffffffffu, s, o);
        if (lane == 0) sm[warp] = s;
        __syncthreads();
        if (tid == 0) {
            float tot = 0.0f;
#pragma unroll
            for (int w = 0; w < THREADS / 32; w++) tot += sm[w];
            int nb = 0;
#pragma unroll
            for (int bi = 0; bi < BB; bi++) nb += num_boxes[bi];
            out[0] = tot / (float)nb;
            g_count = 0;  // reset for next graph replay
        }
    }
}

extern "C" void kernel_launch(void* const* d_in, const int* in_sizes, int n_in,
                              void* d_out, int out_size) {
    const float* y_fcn     = (const float*)d_in[0];  // [B, NCH*NCLS, H, W]
    const float* im_data   = (const float*)d_in[1];  // [B, NCH, H, W]
    // d_in[2] = im_info (unused)
    const int*   gt_boxes  = (const int*)d_in[3];    // [B, MAXB, 5]
    const int*   num_boxes = (const int*)d_in[4];    // [B]
    float*       out       = (float*)d_out;

    dim3 grid(BB * MAXB, STRIPS);
    sel_fused_kernel<<<grid, THREADS>>>(y_fcn, im_data, gt_boxes, num_boxes, out);
}

// round 6
// speedup vs baseline: 1.4004x; 1.4004x over previous
#include <cuda_runtime.h>

#define BB 4
#define NCH 3
#define NCLS 20
#define HH 512
#define WW 512
#define MAXB 50
#define STRIPS 16
#define THREADS 256
#define NBLK (BB * MAXB * STRIPS)

__device__ float g_acc = 0.0f;
__device__ int g_count = 0;

__global__ void sel_fused_kernel(const float* __restrict__ y_fcn,
                                 const float* __restrict__ im_data,
                                 const int* __restrict__ gt_boxes,
                                 const int* __restrict__ num_boxes,
                                 float* __restrict__ out) {
    const int boxid = blockIdx.x;          // 0 .. B*MAXB-1
    const int strip = blockIdx.y;          // 0 .. STRIPS-1
    const int b = boxid / MAXB;
    const int j = boxid % MAXB;
    const int tid = threadIdx.x;
    const int lane = tid & 31;
    const int warp = tid >> 5;

    float acc = 0.0f;
    float denom = 1.0f;
    bool valid = (j < num_boxes[b]);

    int x1 = 0, r0 = 0, r1 = 0, wid = 0;
    const float* im0 = nullptr;
    const float* yf0 = nullptr;

    if (valid) {
        const int* g = gt_boxes + (size_t)boxid * 5;
        x1 = g[0];
        const int y1 = g[1], x2 = g[2], y2 = g[3], cls = g[4];
        const int hgt = y2 - y1;
        wid = x2 - x1;
        if (hgt > 0 && wid > 0) {
            const int rows_per = (hgt + STRIPS - 1) / STRIPS;
            r0 = y1 + strip * rows_per;
            r1 = min(r0 + rows_per, y2);
            denom = (float)(NCH * hgt * wid);
            const size_t plane = (size_t)HH * WW;
            im0 = im_data + (size_t)b * NCH * plane;
            yf0 = y_fcn + ((size_t)b * NCLS + cls) * NCH * plane;
        } else {
            valid = false;
        }
    }

    if (valid && r0 < r1) {
        const int plane = HH * WW;
        if (wid >= THREADS) {
            // wide boxes: threads stride columns within each row (no div/mod)
            for (int r = r0; r < r1; r++) {
                const int rowoff = r * WW + x1;
                for (int c = tid; c < wid; c += THREADS) {
                    const int off = rowoff + c;
#pragma unroll
                    for (int n = 0; n < NCH; n++) {
                        const float d = __ldg(im0 + n * plane + off)
                                      - __ldg(yf0 + n * plane + off);
                        acc += d * d;
                    }
                }
            }
        } else {
            // narrow boxes: flatten (row, col) so all threads stay busy
            const int total = (r1 - r0) * wid;
            for (int idx = tid; idx < total; idx += THREADS) {
                const int rr = idx / wid;
                const int cc = idx - rr * wid;
                const int off = (r0 + rr) * WW + x1 + cc;
#pragma unroll
                for (int n = 0; n < NCH; n++) {
                    const float d = __ldg(im0 + n * plane + off)
                                  - __ldg(yf0 + n * plane + off);
                    acc += d * d;
                }
            }
        }
    }

    // block reduction
    __shared__ float sm[THREADS / 32];
#pragma unroll
    for (int o = 16; o > 0; o >>= 1)
        acc += __shfl_down_sync(0xffffffffu, acc, o);
    if (lane == 0) sm[warp] = acc;
    __syncthreads();

    __shared__ bool is_last;
    if (tid == 0) {
        float s = 0.0f;
#pragma unroll
        for (int w = 0; w < THREADS / 32; w++) s += sm[w];
        if (s != 0.0f) atomicAdd(&g_acc, s / denom);
        __threadfence();
        const int ticket = atomicAdd(&g_count, 1);
        is_last = (ticket == NBLK - 1);
    }
    __syncthreads();

    if (is_last && tid == 0) {
        // all prior atomicAdds to g_acc are ordered before their tickets;
        // read via atomic to get the coherent L2 value.
        const float tot = atomicAdd(&g_acc, 0.0f);
        int nb = 0;
#pragma unroll
        for (int bi = 0; bi < BB; bi++) nb += num_boxes[bi];
        out[0] = tot / (float)nb;
        // reset state for the next graph replay (deterministic per call)
        g_acc = 0.0f;
        g_count = 0;
    }
}

extern "C" void kernel_launch(void* const* d_in, const int* in_sizes, int n_in,
                              void* d_out, int out_size) {
    const float* y_fcn     = (const float*)d_in[0];  // [B, NCH*NCLS, H, W]
    const float* im_data   = (const float*)d_in[1];  // [B, NCH, H, W]
    // d_in[2] = im_info (unused)
    const int*   gt_boxes  = (const int*)d_in[3];    // [B, MAXB, 5]
    const int*   num_boxes = (const int*)d_in[4];    // [B]
    float*       out       = (float*)d_out;

    dim3 grid(BB * MAXB, STRIPS);
    sel_fused_kernel<<<grid, THREADS>>>(y_fcn, im_data, gt_boxes, num_boxes, out);
}